// round 12
// baseline (speedup 1.0000x reference)
#include <cuda_runtime.h>
#include <cuda_bf16.h>
#include <cuda_fp16.h>
#include <stdint.h>

#define H 64

static const int MAXN = 100352;   // N = 100000 in dataset, padded
static const int MAXE = 1605632;  // E = 1600000 in dataset, padded
static const int MAX_CHUNKS = (MAXN + 255) / 256;

// ---- device scratch (allocation-free contract: __device__ globals).
// Self-resetting across graph replays: g_cnt zeroed by its reader (scan),
// g_cur rewritten by the offsets phase each call, g_bagg plain-stored,
// barriers use monotonic generation counters. Zero-init at module load
// makes the first (eager correctness) call correct too.
__device__ __align__(16) __half g_hh[(size_t)MAXN * H];  // h in fp16
__device__ float g_ex[MAXN];                             // exp(relu(agg).w2)
__device__ float g_rz[MAXN];                             // 1 / Z per row
__device__ int g_cnt[MAXN];                              // per-row edge count
__device__ int g_part[MAXN];                             // within-chunk excl
__device__ int g_bagg[MAX_CHUNKS + 32];                  // chunk aggregates
__device__ int g_start[MAXN + 1];                        // CSR row starts
__device__ int g_cur[MAXN];                              // scatter cursors
__device__ __align__(8) int2 g_ecsr[MAXE];               // CSR {col, v_bits}

// two barrier domains (gen-based: never need reset)
__device__ unsigned g_bc_csr = 0, g_bg_csr = 0;
__device__ unsigned g_bc_all = 0, g_bg_all = 0;

__device__ __forceinline__ void grid_bar(unsigned* cnt, unsigned* gen,
                                         int nparts) {
    __syncthreads();
    if (threadIdx.x == 0) {
        __threadfence();
        unsigned g = *(volatile unsigned*)gen;
        if (atomicAdd(cnt, 1u) == (unsigned)nparts - 1u) {
            *cnt = 0;
            __threadfence();
            *(volatile unsigned*)gen = g + 1u;
        } else {
            while (*(volatile unsigned*)gen == g) __nanosleep(32);
        }
        __threadfence();
    }
    __syncthreads();
}

__device__ __forceinline__ uint32_t f2tf32(float f) {
    uint32_t r;
    asm("cvt.rna.tf32.f32 %0, %1;" : "=r"(r) : "f"(f));
    return r;
}
__device__ __forceinline__ void mma_tf32(float c[4], uint32_t a0, uint32_t a1,
                                         uint32_t a2, uint32_t a3, uint32_t b0,
                                         uint32_t b1) {
    asm volatile(
        "mma.sync.aligned.m16n8k8.row.col.f32.tf32.tf32.f32 "
        "{%0,%1,%2,%3}, {%4,%5,%6,%7}, {%8,%9}, {%0,%1,%2,%3};"
        : "+f"(c[0]), "+f"(c[1]), "+f"(c[2]), "+f"(c[3])
        : "r"(a0), "r"(a1), "r"(a2), "r"(a3), "r"(b0), "r"(b1));
}

// =============== single persistent kernel: everything ===============
// Blocks [0,Gb): persistent tf32 GEMM (BM=64, BN=64, warp tile 16x32).
// Blocks [Gb,nb): hist -> scan -> offsets -> scatter (bar_csr between).
// Then bar_all joins both roles; all blocks run agg|z|final.
__global__ void __launch_bounds__(256, 4) mega_kernel(
    const float* __restrict__ feat, const float* __restrict__ W,
    const float* __restrict__ bias, const int* __restrict__ row_idx,
    const int* __restrict__ col_idx, const float* __restrict__ vv,
    const float* __restrict__ wmlp, float* __restrict__ out, int N, int F,
    int E, int nblocks, int Gb) {
    __shared__ uint32_t sA[8 * 260];  // GEMM A staging (8.3 KB)
    __shared__ int sred[8];
    __shared__ int s_off;
    int tid = threadIdx.x;
    int lane = tid & 31, wid = tid >> 5;
    int bid = blockIdx.x;
    int ncsr = nblocks - Gb;

    if (bid < Gb) {
        // ---------------- GEMM role ----------------
        int gid = lane >> 2, tig = lane & 3;
        int mbase = (wid >> 1) * 16;
        int nbase = (wid & 1) * 32;
        int ntiles = (N + 63) >> 6;
        for (int t = bid; t < ntiles; t += Gb) {
            int rowBase = t * 64;
            float acc[4][4];
#pragma unroll
            for (int nt = 0; nt < 4; nt++)
#pragma unroll
                for (int j = 0; j < 4; j++) acc[nt][j] = 0.0f;

            int nkb = F / 32;
            for (int kb = 0; kb < nkb; kb++) {
                __syncthreads();
#pragma unroll
                for (int i = 0; i < 2; i++) {
                    int fid = i * 256 + tid;
                    int row = fid >> 3;
                    int q = fid & 7;
                    int grow = rowBase + row;
                    float4 a = make_float4(0.f, 0.f, 0.f, 0.f);
                    if (grow < N)
                        a = ((const float4*)(feat + (size_t)grow * F +
                                             kb * 32))[q];
                    uint32_t* dst = sA + q * 260 + row * 4;
                    dst[0] = f2tf32(a.x);
                    dst[1] = f2tf32(a.y);
                    dst[2] = f2tf32(a.z);
                    dst[3] = f2tf32(a.w);
                }
                __syncthreads();
#pragma unroll
                for (int ks = 0; ks < 4; ks++) {
                    int kc0 = ks * 2, kc1 = kc0 + 1;
                    int k0 = kb * 32 + kc0 * 4 + tig;
                    int k1 = k0 + 4;
                    uint32_t b0[4], b1[4];
#pragma unroll
                    for (int nt = 0; nt < 4; nt++) {
                        int c = nbase + nt * 8 + gid;
                        b0[nt] = f2tf32(__ldg(W + (size_t)k0 * H + c));
                        b1[nt] = f2tf32(__ldg(W + (size_t)k1 * H + c));
                    }
                    int r = mbase + gid;
                    uint32_t a0 = sA[kc0 * 260 + r * 4 + tig];
                    uint32_t a1 = sA[kc0 * 260 + (r + 8) * 4 + tig];
                    uint32_t a2 = sA[kc1 * 260 + r * 4 + tig];
                    uint32_t a3 = sA[kc1 * 260 + (r + 8) * 4 + tig];
#pragma unroll
                    for (int nt = 0; nt < 4; nt++)
                        mma_tf32(acc[nt], a0, a1, a2, a3, b0[nt], b1[nt]);
                }
            }
            int r0 = rowBase + mbase + gid;
            int r1 = r0 + 8;
#pragma unroll
            for (int nt = 0; nt < 4; nt++) {
                int c = nbase + nt * 8 + 2 * tig;
                float bx = __ldg(bias + c), by = __ldg(bias + c + 1);
                if (r0 < N)
                    *(__half2*)&g_hh[(size_t)r0 * H + c] =
                        __floats2half2_rn(acc[nt][0] + bx, acc[nt][1] + by);
                if (r1 < N)
                    *(__half2*)&g_hh[(size_t)r1 * H + c] =
                        __floats2half2_rn(acc[nt][2] + bx, acc[nt][3] + by);
            }
        }
        // GEMM done: fall through to bar_all below.
    } else {
        // ---------------- CSR role ----------------
        int cbid = bid - Gb;
        int i0 = cbid * 256 + tid;
        int stride = ncsr * 256;
        int E4 = E >> 2;

        // S0: hist (REDG, no return)
        {
            const int4* r4 = (const int4*)row_idx;
            for (int e = i0; e < E4; e += stride) {
                int4 r = r4[e];
                atomicAdd(&g_cnt[r.x], 1);
                atomicAdd(&g_cnt[r.y], 1);
                atomicAdd(&g_cnt[r.z], 1);
                atomicAdd(&g_cnt[r.w], 1);
            }
            for (int e = E4 * 4 + i0; e < E; e += stride)
                atomicAdd(&g_cnt[row_idx[e]], 1);
        }
        grid_bar(&g_bc_csr, &g_bg_csr, ncsr);

        // S1: per-chunk (256-wide) scan; self-reset g_cnt
        int nchunk = (N + 255) >> 8;
        for (int ch = cbid; ch < nchunk; ch += ncsr) {
            __syncthreads();
            int i = ch * 256 + tid;
            int c = (i < N) ? g_cnt[i] : 0;
            if (i < N) g_cnt[i] = 0;
            int x = c;
#pragma unroll
            for (int off = 1; off < 32; off <<= 1) {
                int t = __shfl_up_sync(0xFFFFFFFFu, x, off);
                if (lane >= off) x += t;
            }
            if (lane == 31) sred[wid] = x;
            __syncthreads();
            if (wid == 0) {
                int s = (lane < 8) ? sred[lane] : 0;
#pragma unroll
                for (int off = 1; off < 8; off <<= 1) {
                    int t = __shfl_up_sync(0xFFFFFFFFu, s, off);
                    if (lane >= off) s += t;
                }
                if (lane < 8) sred[lane] = s;
            }
            __syncthreads();
            int xincl = x + ((wid > 0) ? sred[wid - 1] : 0);
            if (i < N) g_part[i] = xincl - c;  // exclusive within chunk
            if (tid == 255) g_bagg[ch] = xincl;
        }
        grid_bar(&g_bc_csr, &g_bg_csr, ncsr);

        // S2: chunk offsets -> g_start, g_cur
        for (int ch = cbid; ch < nchunk; ch += ncsr) {
            __syncthreads();
            int partial = 0;
            for (int j = tid; j < ch; j += 256) partial += g_bagg[j];
#pragma unroll
            for (int o = 16; o; o >>= 1)
                partial += __shfl_xor_sync(0xFFFFFFFFu, partial, o);
            if (lane == 0) sred[wid] = partial;
            __syncthreads();
            if (tid == 0) {
                int t = 0;
#pragma unroll
                for (int j = 0; j < 8; j++) t += sred[j];
                s_off = t;
            }
            __syncthreads();
            int i = ch * 256 + tid;
            if (i < N) {
                int st = s_off + g_part[i];
                g_start[i] = st;
                g_cur[i] = st;
            }
            if (i == N - 1) g_start[N] = E;
        }
        grid_bar(&g_bc_csr, &g_bg_csr, ncsr);

        // S3: scatter via atomic cursors; 8B {col, v_bits} records
        {
            const int4* r4 = (const int4*)row_idx;
            const int4* c4 = (const int4*)col_idx;
            const float4* v4 = (const float4*)vv;
            for (int e = i0; e < E4; e += stride) {
                int4 r = r4[e];
                int4 c = c4[e];
                float4 v = v4[e];
                int p0 = atomicAdd(&g_cur[r.x], 1);
                g_ecsr[p0] = make_int2(c.x, __float_as_int(v.x));
                int p1 = atomicAdd(&g_cur[r.y], 1);
                g_ecsr[p1] = make_int2(c.y, __float_as_int(v.y));
                int p2 = atomicAdd(&g_cur[r.z], 1);
                g_ecsr[p2] = make_int2(c.z, __float_as_int(v.z));
                int p3 = atomicAdd(&g_cur[r.w], 1);
                g_ecsr[p3] = make_int2(c.w, __float_as_int(v.w));
            }
            for (int e = E4 * 4 + i0; e < E; e += stride) {
                int p = atomicAdd(&g_cur[row_idx[e]], 1);
                g_ecsr[p] = make_int2(col_idx[e], __float_as_int(vv[e]));
            }
        }
    }

    // ---- join: GEMM done AND CSR built ----
    grid_bar(&g_bc_all, &g_bg_all, nblocks);

    // S4: agg + relu + dot(w2) + exp  (warp per row, strided over grid)
    {
        int half = lane >> 4;
        int seg = lane & 15;
        int gw = (bid * 256 + tid) >> 5;
        int nw = nblocks * 8;
        for (int w = gw; w < N; w += nw) {
            int s = g_start[w];
            int eend = g_start[w + 1];
            float4 acc = make_float4(0.f, 0.f, 0.f, 0.f);
            for (int p = s + half; p < eend; p += 2) {
                int2 ed = g_ecsr[p];  // broadcast within half-warp
                float v = __int_as_float(ed.y);
                uint2 u = *(const uint2*)(g_hh + (size_t)ed.x * H + seg * 4);
                float2 f01 = __half22float2(*(const __half2*)&u.x);
                float2 f23 = __half22float2(*(const __half2*)&u.y);
                acc.x = fmaf(v, f01.x, acc.x);
                acc.y = fmaf(v, f01.y, acc.y);
                acc.z = fmaf(v, f23.x, acc.z);
                acc.w = fmaf(v, f23.y, acc.w);
            }
            acc.x += __shfl_down_sync(0xFFFFFFFFu, acc.x, 16);
            acc.y += __shfl_down_sync(0xFFFFFFFFu, acc.y, 16);
            acc.z += __shfl_down_sync(0xFFFFFFFFu, acc.z, 16);
            acc.w += __shfl_down_sync(0xFFFFFFFFu, acc.w, 16);
            float pd = 0.0f;
            if (half == 0) {
                float4 w2 = *(const float4*)(wmlp + H + seg * 4);
                pd = fmaxf(acc.x, 0.f) * w2.x + fmaxf(acc.y, 0.f) * w2.y +
                     fmaxf(acc.z, 0.f) * w2.z + fmaxf(acc.w, 0.f) * w2.w;
            }
#pragma unroll
            for (int o = 8; o; o >>= 1)
                pd += __shfl_down_sync(0xFFFFFFFFu, pd, o);
            if (lane == 0) g_ex[w] = __expf(pd);
        }
    }
    grid_bar(&g_bc_all, &g_bg_all, nblocks);

    // S5: per-row Z; store 1/Z
    {
        int gw = (bid * 256 + tid) >> 5;
        int nw = nblocks * 8;
        for (int w = gw; w < N; w += nw) {
            int s = g_start[w];
            int eend = g_start[w + 1];
            if (s == eend) continue;
            float z = 0.0f;
            for (int p = s + lane; p < eend; p += 32) z += g_ex[g_ecsr[p].x];
#pragma unroll
            for (int o = 16; o; o >>= 1)
                z += __shfl_xor_sync(0xFFFFFFFFu, z, o);
            if (lane == 0) g_rz[w] = 1.0f / z;
        }
    }
    grid_bar(&g_bc_all, &g_bg_all, nblocks);

    // S6: final in ORIGINAL edge order (coalesced): out = v + ex*rz
    {
        int i = bid * 256 + tid;
        int stride = nblocks * 256;
        int E4 = E >> 2;
        const int4* r4 = (const int4*)row_idx;
        const int4* c4 = (const int4*)col_idx;
        const float4* v4 = (const float4*)vv;
        float4* o4 = (float4*)out;
        for (int e = i; e < E4; e += stride) {
            int4 r = r4[e];
            int4 c = c4[e];
            float4 v = v4[e];
            float4 o;
            o.x = fmaf(g_ex[c.x], g_rz[r.x], v.x);
            o.y = fmaf(g_ex[c.y], g_rz[r.y], v.y);
            o.z = fmaf(g_ex[c.z], g_rz[r.z], v.z);
            o.w = fmaf(g_ex[c.w], g_rz[r.w], v.w);
            o4[e] = o;
        }
        for (int e = E4 * 4 + i; e < E; e += stride)
            out[e] = fmaf(g_ex[col_idx[e]], g_rz[row_idx[e]], vv[e]);
    }
}

// ---------------------------------------------------------------- launch
extern "C" void kernel_launch(void* const* d_in, const int* in_sizes, int n_in,
                              void* d_out, int out_size) {
    const float* feat = (const float*)d_in[0];
    const float* vv = (const float*)d_in[1];
    const float* W = (const float*)d_in[2];
    const float* bg = (const float*)d_in[3];
    const float* wm = (const float*)d_in[4];
    // d_in[5] = b_mlp: cancels in softmax; unused.
    const int* vidx = (const int*)d_in[6];  // int32 (JAX x64 disabled)

    int F = in_sizes[2] / H;  // 256
    int N = in_sizes[0] / F;  // 100000
    int E = in_sizes[1];      // 1600000
    const int* row_idx = vidx;
    const int* col_idx = vidx + E;
    float* out = (float*)d_out;

    // grid: all blocks must be co-resident (persistent kernel)
    int smcount = 0, bpsm = 0;
    cudaDeviceGetAttribute(&smcount, cudaDevAttrMultiProcessorCount, 0);
    cudaOccupancyMaxActiveBlocksPerMultiprocessor(&bpsm, mega_kernel, 256, 0);
    if (bpsm < 1) bpsm = 1;
    int nblocks = smcount * bpsm;
    if (nblocks < 2) nblocks = 2;
    int Gb = nblocks / 2;  // half GEMM, half CSR

    mega_kernel<<<nblocks, 256>>>(feat, W, bg, row_idx, col_idx, vv, wm, out,
                                  N, F, E, nblocks, Gb);
}

// round 13
// speedup vs baseline: 1.3420x; 1.3420x over previous
#include <cuda_runtime.h>
#include <cuda_bf16.h>
#include <cuda_fp16.h>
#include <stdint.h>

#define H 64

static const int MAXN = 100352;   // N = 100000 in dataset, padded
static const int MAXE = 1605632;  // E = 1600000 in dataset, padded
static const int MAX_CHUNKS = (MAXN + 255) / 256;

// ---- device scratch (allocation-free contract: __device__ globals).
// Self-resetting across graph replays: g_cnt zeroed by its reader in the
// mega kernel's scan phase; g_bagg plain-stored; barriers use monotonic
// generation counters. Zero-init at module load covers the first call.
__device__ __align__(16) __half g_hh[(size_t)MAXN * H];  // h in fp16
__device__ float g_ex[MAXN];                             // exp(relu(agg).w2)
__device__ float g_rz[MAXN];                             // 1 / Z per row
__device__ int g_cnt[MAXN];                              // per-row edge count
__device__ int g_part[MAXN];                             // within-chunk excl
__device__ int g_bagg[MAX_CHUNKS + 32];                  // chunk aggregates
__device__ int g_start[MAXN + 1];                        // CSR row starts
__device__ int g_rank[MAXE];                             // within-row rank
__device__ __align__(8) int2 g_ecsr[MAXE];               // CSR {col, v_bits}

// grid barrier state (gen-based: never needs reset)
__device__ unsigned g_bcount = 0;
__device__ unsigned g_bgen = 0;

__device__ __forceinline__ void grid_bar(int nblocks) {
    __syncthreads();
    if (threadIdx.x == 0) {
        __threadfence();
        unsigned gen = *(volatile unsigned*)&g_bgen;
        if (atomicAdd(&g_bcount, 1u) == (unsigned)nblocks - 1u) {
            g_bcount = 0;
            __threadfence();
            *(volatile unsigned*)&g_bgen = gen + 1u;
        } else {
            while (*(volatile unsigned*)&g_bgen == gen) __nanosleep(32);
        }
        __threadfence();
    }
    __syncthreads();
}

__device__ __forceinline__ uint32_t f2tf32(float f) {
    uint32_t r;
    asm("cvt.rna.tf32.f32 %0, %1;" : "=r"(r) : "f"(f));
    return r;
}
__device__ __forceinline__ void mma_tf32(float c[4], uint32_t a0, uint32_t a1,
                                         uint32_t a2, uint32_t a3, uint32_t b0,
                                         uint32_t b1) {
    asm volatile(
        "mma.sync.aligned.m16n8k8.row.col.f32.tf32.tf32.f32 "
        "{%0,%1,%2,%3}, {%4,%5,%6,%7}, {%8,%9}, {%0,%1,%2,%3};"
        : "+f"(c[0]), "+f"(c[1]), "+f"(c[2]), "+f"(c[3])
        : "r"(a0), "r"(a1), "r"(a2), "r"(a3), "r"(b0), "r"(b1));
}

// -------------------------------------- fused tf32 GEMM | hist (block spec)
// Blocks [0, G): GEMM h = feat@W + b, fp16 out (128x64 tile, 8 warps,
// m16n8k8). W tile (32x64) staged per-kb in smem as tf32 with swizzle
// (k>>2)*256 + n*4 + (k&3) -> fragment LDS are conflict-free, replacing
// 256 scalar LDGs per thread. Blocks [G, ...): hist.
__global__ void __launch_bounds__(256) gemm_hist_kernel(
    const float* __restrict__ feat, const float* __restrict__ W,
    const float* __restrict__ bias, const int* __restrict__ row_idx, int N,
    int F, int E, int G) {
    extern __shared__ uint32_t smem[];
    uint32_t* sA = smem;           // 8 * 516 words
    uint32_t* sW = smem + 8 * 516; // 2048 words (32x64 tf32 tile)

    if (blockIdx.x >= G) {
        int hb = blockIdx.x - G;
        int nhb = gridDim.x - G;
        int i = hb * blockDim.x + threadIdx.x;
        int stride = nhb * blockDim.x;
        int E4 = E >> 2;
        const int4* r4 = (const int4*)row_idx;
        for (int e = i; e < E4; e += stride) {
            int4 r = r4[e];
            int base = e * 4;
            g_rank[base + 0] = atomicAdd(&g_cnt[r.x], 1);
            g_rank[base + 1] = atomicAdd(&g_cnt[r.y], 1);
            g_rank[base + 2] = atomicAdd(&g_cnt[r.z], 1);
            g_rank[base + 3] = atomicAdd(&g_cnt[r.w], 1);
        }
        for (int e = E4 * 4 + i; e < E; e += stride)
            g_rank[e] = atomicAdd(&g_cnt[row_idx[e]], 1);
        return;
    }

    int tid = threadIdx.x;
    int lane = tid & 31, wid = tid >> 5;
    int gid = lane >> 2, tig = lane & 3;
    int mbase = (wid >> 1) * 32;
    int nbase = (wid & 1) * 32;
    int rowBase = blockIdx.x * 128;

    float acc[2][4][4];
#pragma unroll
    for (int mt = 0; mt < 2; mt++)
#pragma unroll
        for (int nt = 0; nt < 4; nt++)
#pragma unroll
            for (int j = 0; j < 4; j++) acc[mt][nt][j] = 0.0f;

    int nkb = F / 32;
    for (int kb = 0; kb < nkb; kb++) {
        __syncthreads();
        // stage A chunk: 128 rows x 32 k
#pragma unroll
        for (int i = 0; i < 4; i++) {
            int fid = i * 256 + tid;
            int row = fid >> 3;
            int q = fid & 7;
            int grow = rowBase + row;
            float4 a = make_float4(0.f, 0.f, 0.f, 0.f);
            if (grow < N)
                a = ((const float4*)(feat + (size_t)grow * F + kb * 32))[q];
            uint32_t* dst = sA + q * 516 + row * 4;
            dst[0] = f2tf32(a.x);
            dst[1] = f2tf32(a.y);
            dst[2] = f2tf32(a.z);
            dst[3] = f2tf32(a.w);
        }
        // stage W tile: 32 k-rows x 64 cols (2 float4 per thread)
#pragma unroll
        for (int it = 0; it < 2; it++) {
            int idx4 = it * 256 + tid;        // 0..511
            int k = idx4 >> 4;                // 0..31 (local k row)
            int n4 = (idx4 & 15) * 4;
            float4 w4 =
                ((const float4*)(W + (size_t)(kb * 32 + k) * H))[idx4 & 15];
            uint32_t base = (k >> 2) * 256 + (k & 3);
            sW[base + (n4 + 0) * 4] = f2tf32(w4.x);
            sW[base + (n4 + 1) * 4] = f2tf32(w4.y);
            sW[base + (n4 + 2) * 4] = f2tf32(w4.z);
            sW[base + (n4 + 3) * 4] = f2tf32(w4.w);
        }
        __syncthreads();

#pragma unroll
        for (int ks = 0; ks < 4; ks++) {
            int kc0 = ks * 2, kc1 = kc0 + 1;
            uint32_t b0[4], b1[4];
#pragma unroll
            for (int nt = 0; nt < 4; nt++) {
                int c = nbase + nt * 8 + gid;
                b0[nt] = sW[kc0 * 256 + c * 4 + tig];
                b1[nt] = sW[kc1 * 256 + c * 4 + tig];
            }
#pragma unroll
            for (int mt = 0; mt < 2; mt++) {
                int r = mbase + mt * 16 + gid;
                uint32_t a0 = sA[kc0 * 516 + r * 4 + tig];
                uint32_t a1 = sA[kc0 * 516 + (r + 8) * 4 + tig];
                uint32_t a2 = sA[kc1 * 516 + r * 4 + tig];
                uint32_t a3 = sA[kc1 * 516 + (r + 8) * 4 + tig];
#pragma unroll
                for (int nt = 0; nt < 4; nt++)
                    mma_tf32(acc[mt][nt], a0, a1, a2, a3, b0[nt], b1[nt]);
            }
        }
    }

#pragma unroll
    for (int mt = 0; mt < 2; mt++) {
        int r0 = rowBase + mbase + mt * 16 + gid;
        int r1 = r0 + 8;
#pragma unroll
        for (int nt = 0; nt < 4; nt++) {
            int c = nbase + nt * 8 + 2 * tig;
            float bx = __ldg(bias + c), by = __ldg(bias + c + 1);
            if (r0 < N)
                *(__half2*)&g_hh[(size_t)r0 * H + c] =
                    __floats2half2_rn(acc[mt][nt][0] + bx,
                                      acc[mt][nt][1] + by);
            if (r1 < N)
                *(__half2*)&g_hh[(size_t)r1 * H + c] =
                    __floats2half2_rn(acc[mt][nt][2] + bx,
                                      acc[mt][nt][3] + by);
        }
    }
}

// ---------------------- persistent mega kernel: scan|scatter|agg|z|final
__global__ void __launch_bounds__(256, 6) mega_kernel(
    const int* __restrict__ row_idx, const int* __restrict__ col_idx,
    const float* __restrict__ vv, const float* __restrict__ wmlp,
    float* __restrict__ out, int N, int E, int nblocks) {
    __shared__ int sred[8];
    __shared__ int s_off;
    int tid = threadIdx.x;
    int lane = tid & 31, wid = tid >> 5;
    int bid = blockIdx.x;
    int nchunk = (N + 255) / 256;

    // ---- S1: per-chunk scan of g_cnt; self-reset g_cnt
    if (bid < nchunk) {
        int i = bid * 256 + tid;
        int c = (i < N) ? g_cnt[i] : 0;
        if (i < N) g_cnt[i] = 0;
        int x = c;
#pragma unroll
        for (int off = 1; off < 32; off <<= 1) {
            int t = __shfl_up_sync(0xFFFFFFFFu, x, off);
            if (lane >= off) x += t;
        }
        if (lane == 31) sred[wid] = x;
        __syncthreads();
        if (wid == 0) {
            int s = (lane < 8) ? sred[lane] : 0;
#pragma unroll
            for (int off = 1; off < 8; off <<= 1) {
                int t = __shfl_up_sync(0xFFFFFFFFu, s, off);
                if (lane >= off) s += t;
            }
            if (lane < 8) sred[lane] = s;
        }
        __syncthreads();
        int xincl = x + ((wid > 0) ? sred[wid - 1] : 0);
        if (i < N) g_part[i] = xincl - c;  // exclusive within chunk
        if (tid == 255) g_bagg[bid] = xincl;
    }
    grid_bar(nblocks);

    // ---- S2: chunk offsets -> g_start
    if (bid < nchunk) {
        int partial = 0;
        for (int j = tid; j < bid; j += 256) partial += g_bagg[j];
#pragma unroll
        for (int o = 16; o; o >>= 1)
            partial += __shfl_xor_sync(0xFFFFFFFFu, partial, o);
        if (lane == 0) sred[wid] = partial;
        __syncthreads();
        if (tid == 0) {
            int t = 0;
#pragma unroll
            for (int j = 0; j < 8; j++) t += sred[j];
            s_off = t;
        }
        __syncthreads();
        int i = bid * 256 + tid;
        if (i < N) g_start[i] = s_off + g_part[i];
        if (i == N - 1) g_start[N] = E;
    }
    grid_bar(nblocks);

    // ---- S3: atomic-free scatter into CSR (8B {col, v_bits})
    {
        int i = bid * 256 + tid;
        int stride = nblocks * 256;
        int E4 = E >> 2;
        const int4* r4 = (const int4*)row_idx;
        const int4* c4 = (const int4*)col_idx;
        const float4* v4 = (const float4*)vv;
        const int4* k4 = (const int4*)g_rank;
        for (int e = i; e < E4; e += stride) {
            int4 r = r4[e];
            int4 c = c4[e];
            float4 v = v4[e];
            int4 k = k4[e];
            g_ecsr[g_start[r.x] + k.x] = make_int2(c.x, __float_as_int(v.x));
            g_ecsr[g_start[r.y] + k.y] = make_int2(c.y, __float_as_int(v.y));
            g_ecsr[g_start[r.z] + k.z] = make_int2(c.z, __float_as_int(v.z));
            g_ecsr[g_start[r.w] + k.w] = make_int2(c.w, __float_as_int(v.w));
        }
        for (int e = E4 * 4 + i; e < E; e += stride)
            g_ecsr[g_start[row_idx[e]] + g_rank[e]] =
                make_int2(col_idx[e], __float_as_int(vv[e]));
    }
    grid_bar(nblocks);

    // ---- S4: agg + relu + dot(w2) + exp  (warp per row)
    {
        int half = lane >> 4;
        int seg = lane & 15;
        int gw = (bid * 256 + tid) >> 5;
        int nw = nblocks * 8;
        for (int w = gw; w < N; w += nw) {
            int s = g_start[w];
            int eend = g_start[w + 1];
            float4 acc = make_float4(0.f, 0.f, 0.f, 0.f);
            for (int p = s + half; p < eend; p += 2) {
                int2 ed = g_ecsr[p];  // broadcast within half-warp
                float v = __int_as_float(ed.y);
                uint2 u = *(const uint2*)(g_hh + (size_t)ed.x * H + seg * 4);
                float2 f01 = __half22float2(*(const __half2*)&u.x);
                float2 f23 = __half22float2(*(const __half2*)&u.y);
                acc.x = fmaf(v, f01.x, acc.x);
                acc.y = fmaf(v, f01.y, acc.y);
                acc.z = fmaf(v, f23.x, acc.z);
                acc.w = fmaf(v, f23.y, acc.w);
            }
            acc.x += __shfl_down_sync(0xFFFFFFFFu, acc.x, 16);
            acc.y += __shfl_down_sync(0xFFFFFFFFu, acc.y, 16);
            acc.z += __shfl_down_sync(0xFFFFFFFFu, acc.z, 16);
            acc.w += __shfl_down_sync(0xFFFFFFFFu, acc.w, 16);
            float pd = 0.0f;
            if (half == 0) {
                float4 w2 = *(const float4*)(wmlp + H + seg * 4);
                pd = fmaxf(acc.x, 0.f) * w2.x + fmaxf(acc.y, 0.f) * w2.y +
                     fmaxf(acc.z, 0.f) * w2.z + fmaxf(acc.w, 0.f) * w2.w;
            }
#pragma unroll
            for (int o = 8; o; o >>= 1)
                pd += __shfl_down_sync(0xFFFFFFFFu, pd, o);
            if (lane == 0) g_ex[w] = __expf(pd);
        }
    }
    grid_bar(nblocks);

    // ---- S5: per-row Z; store 1/Z
    {
        int gw = (bid * 256 + tid) >> 5;
        int nw = nblocks * 8;
        for (int w = gw; w < N; w += nw) {
            int s = g_start[w];
            int eend = g_start[w + 1];
            if (s == eend) continue;
            float z = 0.0f;
            for (int p = s + lane; p < eend; p += 32) z += g_ex[g_ecsr[p].x];
#pragma unroll
            for (int o = 16; o; o >>= 1)
                z += __shfl_xor_sync(0xFFFFFFFFu, z, o);
            if (lane == 0) g_rz[w] = 1.0f / z;
        }
    }
    grid_bar(nblocks);

    // ---- S6: final, original edge order (coalesced): out = v + ex*rz
    {
        int i = bid * 256 + tid;
        int stride = nblocks * 256;
        int E4 = E >> 2;
        const int4* r4 = (const int4*)row_idx;
        const int4* c4 = (const int4*)col_idx;
        const float4* v4 = (const float4*)vv;
        float4* o4 = (float4*)out;
        for (int e = i; e < E4; e += stride) {
            int4 r = r4[e];
            int4 c = c4[e];
            float4 v = v4[e];
            float4 o;
            o.x = fmaf(g_ex[c.x], g_rz[r.x], v.x);
            o.y = fmaf(g_ex[c.y], g_rz[r.y], v.y);
            o.z = fmaf(g_ex[c.z], g_rz[r.z], v.z);
            o.w = fmaf(g_ex[c.w], g_rz[r.w], v.w);
            o4[e] = o;
        }
        for (int e = E4 * 4 + i; e < E; e += stride)
            out[e] = fmaf(g_ex[col_idx[e]], g_rz[row_idx[e]], vv[e]);
    }
}

// ---------------------------------------------------------------- launch
extern "C" void kernel_launch(void* const* d_in, const int* in_sizes, int n_in,
                              void* d_out, int out_size) {
    const float* feat = (const float*)d_in[0];
    const float* vv = (const float*)d_in[1];
    const float* W = (const float*)d_in[2];
    const float* bg = (const float*)d_in[3];
    const float* wm = (const float*)d_in[4];
    // d_in[5] = b_mlp: cancels in softmax; unused.
    const int* vidx = (const int*)d_in[6];  // int32 (JAX x64 disabled)

    int F = in_sizes[2] / H;  // 256
    int N = in_sizes[0] / F;  // 100000
    int E = in_sizes[1];      // 1600000
    const int* row_idx = vidx;
    const int* col_idx = vidx + E;
    float* out = (float*)d_out;

    int G = (N + 127) / 128;  // gemm blocks
    int HB = 1024;            // hist blocks

    int smcount = 0, bpsm = 0;
    cudaDeviceGetAttribute(&smcount, cudaDevAttrMultiProcessorCount, 0);
    cudaOccupancyMaxActiveBlocksPerMultiprocessor(&bpsm, mega_kernel, 256, 0);
    if (bpsm > 6) bpsm = 6;
    if (bpsm < 1) bpsm = 1;
    int nblocks = smcount * bpsm;
    int nchunk = (N + 255) / 256;
    if (nblocks < nchunk) nblocks = nchunk;

    size_t smem = (size_t)(8 * 516 + 2048) * 4;  // A staging + W tile (24.7KB)

    gemm_hist_kernel<<<G + HB, 256, smem>>>(feat, W, bg, row_idx, N, F, E, G);
    mega_kernel<<<nblocks, 256>>>(row_idx, col_idx, vv, wm, out, N, E,
                                  nblocks);
}

// round 14
// speedup vs baseline: 1.3426x; 1.0004x over previous
#include <cuda_runtime.h>
#include <cuda_bf16.h>
#include <cuda_fp16.h>
#include <stdint.h>

#define H 64

static const int MAXN = 100352;   // N = 100000 in dataset, padded
static const int MAXE = 1605632;  // E = 1600000 in dataset, padded
static const int MAX_CHUNKS = (MAXN + 255) / 256;

// ---- device scratch (allocation-free contract: __device__ globals).
// Self-resetting across graph replays: g_cnt zeroed by its reader in the
// mega kernel's scan phase; g_bagg plain-stored; barriers use monotonic
// generation counters. Zero-init at module load covers the first call.
__device__ __align__(16) __half g_hh[(size_t)MAXN * H];  // h in fp16
__device__ float g_ex[MAXN];                             // exp(relu(agg).w2)
__device__ float g_rz[MAXN];                             // 1 / Z per row
__device__ int g_cnt[MAXN];                              // per-row edge count
__device__ int g_part[MAXN];                             // within-chunk excl
__device__ int g_bagg[MAX_CHUNKS + 32];                  // chunk aggregates
__device__ int g_start[MAXN + 1];                        // CSR row starts
__device__ int g_rank[MAXE];                             // within-row rank
__device__ __align__(8) int2 g_ecsr[MAXE];               // CSR {col, v_bits}

// grid barrier state (gen-based: never needs reset)
__device__ unsigned g_bcount = 0;
__device__ unsigned g_bgen = 0;

__device__ __forceinline__ void grid_bar(int nblocks) {
    __syncthreads();
    if (threadIdx.x == 0) {
        __threadfence();
        unsigned gen = *(volatile unsigned*)&g_bgen;
        if (atomicAdd(&g_bcount, 1u) == (unsigned)nblocks - 1u) {
            g_bcount = 0;
            __threadfence();
            *(volatile unsigned*)&g_bgen = gen + 1u;
        } else {
            while (*(volatile unsigned*)&g_bgen == gen) __nanosleep(32);
        }
        __threadfence();
    }
    __syncthreads();
}

__device__ __forceinline__ uint32_t f2tf32(float f) {
    uint32_t r;
    asm("cvt.rna.tf32.f32 %0, %1;" : "=r"(r) : "f"(f));
    return r;
}
__device__ __forceinline__ void mma_tf32(float c[4], uint32_t a0, uint32_t a1,
                                         uint32_t a2, uint32_t a3, uint32_t b0,
                                         uint32_t b1) {
    asm volatile(
        "mma.sync.aligned.m16n8k8.row.col.f32.tf32.tf32.f32 "
        "{%0,%1,%2,%3}, {%4,%5,%6,%7}, {%8,%9}, {%0,%1,%2,%3};"
        : "+f"(c[0]), "+f"(c[1]), "+f"(c[2]), "+f"(c[3])
        : "r"(a0), "r"(a1), "r"(a2), "r"(a3), "r"(b0), "r"(b1));
}

// -------------------------------------- fused tf32 GEMM | hist (block spec)
// Blocks [0, G): GEMM h = feat@W + b, fp16 out (128x64 tile, 8 warps,
// m16n8k8). W tile (32x64) staged per-kb in smem as tf32 with swizzle
// (k>>2)*256 + n*4 + (k&3). Blocks [G, ...): hist.
__global__ void __launch_bounds__(256) gemm_hist_kernel(
    const float* __restrict__ feat, const float* __restrict__ W,
    const float* __restrict__ bias, const int* __restrict__ row_idx, int N,
    int F, int E, int G) {
    extern __shared__ uint32_t smem[];
    uint32_t* sA = smem;            // 8 * 516 words
    uint32_t* sW = smem + 8 * 516;  // 2048 words (32x64 tf32 tile)

    if (blockIdx.x >= G) {
        int hb = blockIdx.x - G;
        int nhb = gridDim.x - G;
        int i = hb * blockDim.x + threadIdx.x;
        int stride = nhb * blockDim.x;
        int E4 = E >> 2;
        const int4* r4 = (const int4*)row_idx;
        for (int e = i; e < E4; e += stride) {
            int4 r = r4[e];
            int base = e * 4;
            g_rank[base + 0] = atomicAdd(&g_cnt[r.x], 1);
            g_rank[base + 1] = atomicAdd(&g_cnt[r.y], 1);
            g_rank[base + 2] = atomicAdd(&g_cnt[r.z], 1);
            g_rank[base + 3] = atomicAdd(&g_cnt[r.w], 1);
        }
        for (int e = E4 * 4 + i; e < E; e += stride)
            g_rank[e] = atomicAdd(&g_cnt[row_idx[e]], 1);
        return;
    }

    int tid = threadIdx.x;
    int lane = tid & 31, wid = tid >> 5;
    int gid = lane >> 2, tig = lane & 3;
    int mbase = (wid >> 1) * 32;
    int nbase = (wid & 1) * 32;
    int rowBase = blockIdx.x * 128;

    float acc[2][4][4];
#pragma unroll
    for (int mt = 0; mt < 2; mt++)
#pragma unroll
        for (int nt = 0; nt < 4; nt++)
#pragma unroll
            for (int j = 0; j < 4; j++) acc[mt][nt][j] = 0.0f;

    int nkb = F / 32;
    for (int kb = 0; kb < nkb; kb++) {
        __syncthreads();
#pragma unroll
        for (int i = 0; i < 4; i++) {
            int fid = i * 256 + tid;
            int row = fid >> 3;
            int q = fid & 7;
            int grow = rowBase + row;
            float4 a = make_float4(0.f, 0.f, 0.f, 0.f);
            if (grow < N)
                a = ((const float4*)(feat + (size_t)grow * F + kb * 32))[q];
            uint32_t* dst = sA + q * 516 + row * 4;
            dst[0] = f2tf32(a.x);
            dst[1] = f2tf32(a.y);
            dst[2] = f2tf32(a.z);
            dst[3] = f2tf32(a.w);
        }
#pragma unroll
        for (int it = 0; it < 2; it++) {
            int idx4 = it * 256 + tid;
            int k = idx4 >> 4;
            int n4 = (idx4 & 15) * 4;
            float4 w4 =
                ((const float4*)(W + (size_t)(kb * 32 + k) * H))[idx4 & 15];
            uint32_t base = (k >> 2) * 256 + (k & 3);
            sW[base + (n4 + 0) * 4] = f2tf32(w4.x);
            sW[base + (n4 + 1) * 4] = f2tf32(w4.y);
            sW[base + (n4 + 2) * 4] = f2tf32(w4.z);
            sW[base + (n4 + 3) * 4] = f2tf32(w4.w);
        }
        __syncthreads();

#pragma unroll
        for (int ks = 0; ks < 4; ks++) {
            int kc0 = ks * 2, kc1 = kc0 + 1;
            uint32_t b0[4], b1[4];
#pragma unroll
            for (int nt = 0; nt < 4; nt++) {
                int c = nbase + nt * 8 + gid;
                b0[nt] = sW[kc0 * 256 + c * 4 + tig];
                b1[nt] = sW[kc1 * 256 + c * 4 + tig];
            }
#pragma unroll
            for (int mt = 0; mt < 2; mt++) {
                int r = mbase + mt * 16 + gid;
                uint32_t a0 = sA[kc0 * 516 + r * 4 + tig];
                uint32_t a1 = sA[kc0 * 516 + (r + 8) * 4 + tig];
                uint32_t a2 = sA[kc1 * 516 + r * 4 + tig];
                uint32_t a3 = sA[kc1 * 516 + (r + 8) * 4 + tig];
#pragma unroll
                for (int nt = 0; nt < 4; nt++)
                    mma_tf32(acc[mt][nt], a0, a1, a2, a3, b0[nt], b1[nt]);
            }
        }
    }

#pragma unroll
    for (int mt = 0; mt < 2; mt++) {
        int r0 = rowBase + mbase + mt * 16 + gid;
        int r1 = r0 + 8;
#pragma unroll
        for (int nt = 0; nt < 4; nt++) {
            int c = nbase + nt * 8 + 2 * tig;
            float bx = __ldg(bias + c), by = __ldg(bias + c + 1);
            if (r0 < N)
                *(__half2*)&g_hh[(size_t)r0 * H + c] =
                    __floats2half2_rn(acc[mt][nt][0] + bx,
                                      acc[mt][nt][1] + by);
            if (r1 < N)
                *(__half2*)&g_hh[(size_t)r1 * H + c] =
                    __floats2half2_rn(acc[mt][nt][2] + bx,
                                      acc[mt][nt][3] + by);
        }
    }
}

// ---------------------- persistent mega kernel: scan|scatter|agg|z|final
__global__ void __launch_bounds__(256, 5) mega_kernel(
    const int* __restrict__ row_idx, const int* __restrict__ col_idx,
    const float* __restrict__ vv, const float* __restrict__ wmlp,
    float* __restrict__ out, int N, int E, int nblocks) {
    __shared__ int sred[8];
    __shared__ int s_off;
    int tid = threadIdx.x;
    int lane = tid & 31, wid = tid >> 5;
    int bid = blockIdx.x;
    int nchunk = (N + 255) / 256;

    // ---- S1: per-chunk scan of g_cnt; self-reset g_cnt
    if (bid < nchunk) {
        int i = bid * 256 + tid;
        int c = (i < N) ? g_cnt[i] : 0;
        if (i < N) g_cnt[i] = 0;
        int x = c;
#pragma unroll
        for (int off = 1; off < 32; off <<= 1) {
            int t = __shfl_up_sync(0xFFFFFFFFu, x, off);
            if (lane >= off) x += t;
        }
        if (lane == 31) sred[wid] = x;
        __syncthreads();
        if (wid == 0) {
            int s = (lane < 8) ? sred[lane] : 0;
#pragma unroll
            for (int off = 1; off < 8; off <<= 1) {
                int t = __shfl_up_sync(0xFFFFFFFFu, s, off);
                if (lane >= off) s += t;
            }
            if (lane < 8) sred[lane] = s;
        }
        __syncthreads();
        int xincl = x + ((wid > 0) ? sred[wid - 1] : 0);
        if (i < N) g_part[i] = xincl - c;  // exclusive within chunk
        if (tid == 255) g_bagg[bid] = xincl;
    }
    grid_bar(nblocks);

    // ---- S2: chunk offsets -> g_start
    if (bid < nchunk) {
        int partial = 0;
        for (int j = tid; j < bid; j += 256) partial += g_bagg[j];
#pragma unroll
        for (int o = 16; o; o >>= 1)
            partial += __shfl_xor_sync(0xFFFFFFFFu, partial, o);
        if (lane == 0) sred[wid] = partial;
        __syncthreads();
        if (tid == 0) {
            int t = 0;
#pragma unroll
            for (int j = 0; j < 8; j++) t += sred[j];
            s_off = t;
        }
        __syncthreads();
        int i = bid * 256 + tid;
        if (i < N) g_start[i] = s_off + g_part[i];
        if (i == N - 1) g_start[N] = E;
    }
    grid_bar(nblocks);

    // ---- S3: atomic-free scatter into CSR (8B {col, v_bits})
    {
        int i = bid * 256 + tid;
        int stride = nblocks * 256;
        int E4 = E >> 2;
        const int4* r4 = (const int4*)row_idx;
        const int4* c4 = (const int4*)col_idx;
        const float4* v4 = (const float4*)vv;
        const int4* k4 = (const int4*)g_rank;
        for (int e = i; e < E4; e += stride) {
            int4 r = r4[e];
            int4 c = c4[e];
            float4 v = v4[e];
            int4 k = k4[e];
            g_ecsr[g_start[r.x] + k.x] = make_int2(c.x, __float_as_int(v.x));
            g_ecsr[g_start[r.y] + k.y] = make_int2(c.y, __float_as_int(v.y));
            g_ecsr[g_start[r.z] + k.z] = make_int2(c.z, __float_as_int(v.z));
            g_ecsr[g_start[r.w] + k.w] = make_int2(c.w, __float_as_int(v.w));
        }
        for (int e = E4 * 4 + i; e < E; e += stride)
            g_ecsr[g_start[row_idx[e]] + g_rank[e]] =
                make_int2(col_idx[e], __float_as_int(vv[e]));
    }
    grid_bar(nblocks);

    // ---- S4: agg + relu + dot(w2) + exp  (warp per row; half-warp per
    //      edge with TWO edges in flight -> MLP 4 per warp)
    {
        int half = lane >> 4;
        int seg = lane & 15;
        int gw = (bid * 256 + tid) >> 5;
        int nw = nblocks * 8;
        for (int w = gw; w < N; w += nw) {
            int s = g_start[w];
            int eend = g_start[w + 1];
            float4 acc0 = make_float4(0.f, 0.f, 0.f, 0.f);
            float4 acc1 = make_float4(0.f, 0.f, 0.f, 0.f);
            int p = s + half;
            for (; p + 2 < eend; p += 4) {
                int2 ed0 = g_ecsr[p];
                int2 ed1 = g_ecsr[p + 2];
                uint2 u0 = *(const uint2*)(g_hh + (size_t)ed0.x * H + seg * 4);
                uint2 u1 = *(const uint2*)(g_hh + (size_t)ed1.x * H + seg * 4);
                float v0 = __int_as_float(ed0.y);
                float v1 = __int_as_float(ed1.y);
                float2 a01 = __half22float2(*(const __half2*)&u0.x);
                float2 a23 = __half22float2(*(const __half2*)&u0.y);
                float2 b01 = __half22float2(*(const __half2*)&u1.x);
                float2 b23 = __half22float2(*(const __half2*)&u1.y);
                acc0.x = fmaf(v0, a01.x, acc0.x);
                acc0.y = fmaf(v0, a01.y, acc0.y);
                acc0.z = fmaf(v0, a23.x, acc0.z);
                acc0.w = fmaf(v0, a23.y, acc0.w);
                acc1.x = fmaf(v1, b01.x, acc1.x);
                acc1.y = fmaf(v1, b01.y, acc1.y);
                acc1.z = fmaf(v1, b23.x, acc1.z);
                acc1.w = fmaf(v1, b23.y, acc1.w);
            }
            if (p < eend) {
                int2 ed = g_ecsr[p];
                uint2 u = *(const uint2*)(g_hh + (size_t)ed.x * H + seg * 4);
                float v = __int_as_float(ed.y);
                float2 f01 = __half22float2(*(const __half2*)&u.x);
                float2 f23 = __half22float2(*(const __half2*)&u.y);
                acc0.x = fmaf(v, f01.x, acc0.x);
                acc0.y = fmaf(v, f01.y, acc0.y);
                acc0.z = fmaf(v, f23.x, acc0.z);
                acc0.w = fmaf(v, f23.y, acc0.w);
            }
            float4 acc;
            acc.x = acc0.x + acc1.x;
            acc.y = acc0.y + acc1.y;
            acc.z = acc0.z + acc1.z;
            acc.w = acc0.w + acc1.w;
            acc.x += __shfl_down_sync(0xFFFFFFFFu, acc.x, 16);
            acc.y += __shfl_down_sync(0xFFFFFFFFu, acc.y, 16);
            acc.z += __shfl_down_sync(0xFFFFFFFFu, acc.z, 16);
            acc.w += __shfl_down_sync(0xFFFFFFFFu, acc.w, 16);
            float pd = 0.0f;
            if (half == 0) {
                float4 w2 = *(const float4*)(wmlp + H + seg * 4);
                pd = fmaxf(acc.x, 0.f) * w2.x + fmaxf(acc.y, 0.f) * w2.y +
                     fmaxf(acc.z, 0.f) * w2.z + fmaxf(acc.w, 0.f) * w2.w;
            }
#pragma unroll
            for (int o = 8; o; o >>= 1)
                pd += __shfl_down_sync(0xFFFFFFFFu, pd, o);
            if (lane == 0) g_ex[w] = __expf(pd);
        }
    }
    grid_bar(nblocks);

    // ---- S5: per-row Z (HALF-warp per row; 16-lane gather); store 1/Z
    {
        int seg = lane & 15;
        int ghw = (bid * 256 + tid) >> 4;  // global half-warp id
        int nhw = nblocks * 16;
        for (int w = ghw; w < N; w += nhw) {
            int s = g_start[w];
            int eend = g_start[w + 1];
            if (s == eend) continue;
            float z = 0.0f;
            for (int p = s + seg; p < eend; p += 16) z += g_ex[g_ecsr[p].x];
#pragma unroll
            for (int o = 8; o; o >>= 1)
                z += __shfl_xor_sync(0xFFFFFFFFu, z, o);
            if (seg == 0) g_rz[w] = 1.0f / z;
        }
    }
    grid_bar(nblocks);

    // ---- S6: final, original edge order (coalesced): out = v + ex*rz
    {
        int i = bid * 256 + tid;
        int stride = nblocks * 256;
        int E4 = E >> 2;
        const int4* r4 = (const int4*)row_idx;
        const int4* c4 = (const int4*)col_idx;
        const float4* v4 = (const float4*)vv;
        float4* o4 = (float4*)out;
        for (int e = i; e < E4; e += stride) {
            int4 r = r4[e];
            int4 c = c4[e];
            float4 v = v4[e];
            float4 o;
            o.x = fmaf(g_ex[c.x], g_rz[r.x], v.x);
            o.y = fmaf(g_ex[c.y], g_rz[r.y], v.y);
            o.z = fmaf(g_ex[c.z], g_rz[r.z], v.z);
            o.w = fmaf(g_ex[c.w], g_rz[r.w], v.w);
            o4[e] = o;
        }
        for (int e = E4 * 4 + i; e < E; e += stride)
            out[e] = fmaf(g_ex[col_idx[e]], g_rz[row_idx[e]], vv[e]);
    }
}

// ---------------------------------------------------------------- launch
extern "C" void kernel_launch(void* const* d_in, const int* in_sizes, int n_in,
                              void* d_out, int out_size) {
    const float* feat = (const float*)d_in[0];
    const float* vv = (const float*)d_in[1];
    const float* W = (const float*)d_in[2];
    const float* bg = (const float*)d_in[3];
    const float* wm = (const float*)d_in[4];
    // d_in[5] = b_mlp: cancels in softmax; unused.
    const int* vidx = (const int*)d_in[6];  // int32 (JAX x64 disabled)

    int F = in_sizes[2] / H;  // 256
    int N = in_sizes[0] / F;  // 100000
    int E = in_sizes[1];      // 1600000
    const int* row_idx = vidx;
    const int* col_idx = vidx + E;
    float* out = (float*)d_out;

    int G = (N + 127) / 128;  // gemm blocks
    int HB = 1024;            // hist blocks

    int smcount = 0, bpsm = 0;
    cudaDeviceGetAttribute(&smcount, cudaDevAttrMultiProcessorCount, 0);
    cudaOccupancyMaxActiveBlocksPerMultiprocessor(&bpsm, mega_kernel, 256, 0);
    if (bpsm > 6) bpsm = 6;
    if (bpsm < 1) bpsm = 1;
    int nblocks = smcount * bpsm;
    int nchunk = (N + 255) / 256;
    if (nblocks < nchunk) nblocks = nchunk;

    size_t smem = (size_t)(8 * 516 + 2048) * 4;  // A staging + W tile (24.7KB)

    gemm_hist_kernel<<<G + HB, 256, smem>>>(feat, W, bg, row_idx, N, F, E, G);
    mega_kernel<<<nblocks, 256>>>(row_idx, col_idx, vv, wm, out, N, E,
                                  nblocks);
}

// round 15
// speedup vs baseline: 1.3748x; 1.0240x over previous
#include <cuda_runtime.h>
#include <cuda_bf16.h>
#include <cuda_fp16.h>
#include <stdint.h>

#define H 64

static const int MAXN = 100352;   // N = 100000 in dataset, padded
static const int MAXE = 1605632;  // E = 1600000 in dataset, padded
static const int MAX_CHUNKS = (MAXN + 255) / 256;

// ---- device scratch (allocation-free contract: __device__ globals).
// Self-resetting across graph replays: g_cnt zeroed by its reader in the
// mega kernel's scan phase; g_bagg plain-stored; barriers use monotonic
// generation counters. Zero-init at module load covers the first call.
__device__ __align__(16) __half g_hh[(size_t)MAXN * H];  // h in fp16
__device__ float g_ex[MAXN];                             // exp(relu(agg).w2)
__device__ float g_rz[MAXN];                             // 1 / Z per row
__device__ int g_cnt[MAXN];                              // per-row edge count
__device__ int g_part[MAXN];                             // within-chunk excl
__device__ int g_bagg[MAX_CHUNKS + 32];                  // chunk aggregates
__device__ int g_start[MAXN + 1];                        // CSR row starts
__device__ int g_rank[MAXE];                             // within-row rank
__device__ __align__(8) int2 g_ecsr[MAXE];               // CSR {col, v_bits}

// grid barrier state (gen-based: never needs reset)
__device__ unsigned g_bcount = 0;
__device__ unsigned g_bgen = 0;

__device__ __forceinline__ void grid_bar(int nblocks) {
    __syncthreads();
    if (threadIdx.x == 0) {
        __threadfence();
        unsigned gen = *(volatile unsigned*)&g_bgen;
        if (atomicAdd(&g_bcount, 1u) == (unsigned)nblocks - 1u) {
            g_bcount = 0;
            __threadfence();
            *(volatile unsigned*)&g_bgen = gen + 1u;
        } else {
            while (*(volatile unsigned*)&g_bgen == gen) __nanosleep(32);
        }
        __threadfence();
    }
    __syncthreads();
}

__device__ __forceinline__ uint32_t f2tf32(float f) {
    uint32_t r;
    asm("cvt.rna.tf32.f32 %0, %1;" : "=r"(r) : "f"(f));
    return r;
}
__device__ __forceinline__ void mma_tf32(float c[4], uint32_t a0, uint32_t a1,
                                         uint32_t a2, uint32_t a3, uint32_t b0,
                                         uint32_t b1) {
    asm volatile(
        "mma.sync.aligned.m16n8k8.row.col.f32.tf32.tf32.f32 "
        "{%0,%1,%2,%3}, {%4,%5,%6,%7}, {%8,%9}, {%0,%1,%2,%3};"
        : "+f"(c[0]), "+f"(c[1]), "+f"(c[2]), "+f"(c[3])
        : "r"(a0), "r"(a1), "r"(a2), "r"(a3), "r"(b0), "r"(b1));
}

// -------------------------------------- fused tf32 GEMM | hist (block spec)
// Blocks [0, G): GEMM h = feat@W + b, fp16 out (128x64 tile, 8 warps,
// m16n8k8), REGISTER-PREFETCH double buffered: kb+1's A/W loads are in
// flight during kb's mma compute. Blocks [G, ...): hist.
__global__ void __launch_bounds__(256) gemm_hist_kernel(
    const float* __restrict__ feat, const float* __restrict__ W,
    const float* __restrict__ bias, const int* __restrict__ row_idx, int N,
    int F, int E, int G) {
    extern __shared__ uint32_t smem[];
    uint32_t* sA = smem;            // 8 * 516 words
    uint32_t* sW = smem + 8 * 516;  // 2048 words (32x64 tf32 tile)

    if (blockIdx.x >= G) {
        int hb = blockIdx.x - G;
        int nhb = gridDim.x - G;
        int i = hb * blockDim.x + threadIdx.x;
        int stride = nhb * blockDim.x;
        int E4 = E >> 2;
        const int4* r4 = (const int4*)row_idx;
        for (int e = i; e < E4; e += stride) {
            int4 r = r4[e];
            int base = e * 4;
            g_rank[base + 0] = atomicAdd(&g_cnt[r.x], 1);
            g_rank[base + 1] = atomicAdd(&g_cnt[r.y], 1);
            g_rank[base + 2] = atomicAdd(&g_cnt[r.z], 1);
            g_rank[base + 3] = atomicAdd(&g_cnt[r.w], 1);
        }
        for (int e = E4 * 4 + i; e < E; e += stride)
            g_rank[e] = atomicAdd(&g_cnt[row_idx[e]], 1);
        return;
    }

    int tid = threadIdx.x;
    int lane = tid & 31, wid = tid >> 5;
    int gid = lane >> 2, tig = lane & 3;
    int mbase = (wid >> 1) * 32;
    int nbase = (wid & 1) * 32;
    int rowBase = blockIdx.x * 128;

    // per-thread load slots
    int aRow = tid >> 3;           // used with 4 strided row groups
    int aQ = tid & 7;
    int wK = tid >> 4;             // W rows 0..15 (+16 on second slot)
    int wQ = tid & 15;

    float acc[2][4][4];
#pragma unroll
    for (int mt = 0; mt < 2; mt++)
#pragma unroll
        for (int nt = 0; nt < 4; nt++)
#pragma unroll
            for (int j = 0; j < 4; j++) acc[mt][nt][j] = 0.0f;

    float4 aPre[4], wPre[2];
    // prologue: prefetch kb = 0
#pragma unroll
    for (int i = 0; i < 4; i++) {
        int row = (i * 256 + tid) >> 3;
        int grow = rowBase + row;
        aPre[i] = make_float4(0.f, 0.f, 0.f, 0.f);
        if (grow < N) aPre[i] = ((const float4*)(feat + (size_t)grow * F))[aQ];
    }
#pragma unroll
    for (int it = 0; it < 2; it++)
        wPre[it] = ((const float4*)(W + (size_t)(it * 16 + wK) * H))[wQ];

    int nkb = F / 32;
    for (int kb = 0; kb < nkb; kb++) {
        __syncthreads();  // previous compute done; smem free
        // commit prefetched tiles to smem (tf32 conversion here)
#pragma unroll
        for (int i = 0; i < 4; i++) {
            int row = (i * 256 + tid) >> 3;
            uint32_t* dst = sA + aQ * 516 + row * 4;
            dst[0] = f2tf32(aPre[i].x);
            dst[1] = f2tf32(aPre[i].y);
            dst[2] = f2tf32(aPre[i].z);
            dst[3] = f2tf32(aPre[i].w);
        }
#pragma unroll
        for (int it = 0; it < 2; it++) {
            int k = it * 16 + wK;
            int n4 = wQ * 4;
            uint32_t base = (k >> 2) * 256 + (k & 3);
            sW[base + (n4 + 0) * 4] = f2tf32(wPre[it].x);
            sW[base + (n4 + 1) * 4] = f2tf32(wPre[it].y);
            sW[base + (n4 + 2) * 4] = f2tf32(wPre[it].z);
            sW[base + (n4 + 3) * 4] = f2tf32(wPre[it].w);
        }
        __syncthreads();

        // issue kb+1 prefetch: these LDGs fly while mma below computes
        if (kb + 1 < nkb) {
            int koff = (kb + 1) * 32;
#pragma unroll
            for (int i = 0; i < 4; i++) {
                int row = (i * 256 + tid) >> 3;
                int grow = rowBase + row;
                aPre[i] = make_float4(0.f, 0.f, 0.f, 0.f);
                if (grow < N)
                    aPre[i] =
                        ((const float4*)(feat + (size_t)grow * F + koff))[aQ];
            }
#pragma unroll
            for (int it = 0; it < 2; it++)
                wPre[it] =
                    ((const float4*)(W + (size_t)(koff + it * 16 + wK) * H))[wQ];
        }

#pragma unroll
        for (int ks = 0; ks < 4; ks++) {
            int kc0 = ks * 2, kc1 = kc0 + 1;
            uint32_t b0[4], b1[4];
#pragma unroll
            for (int nt = 0; nt < 4; nt++) {
                int c = nbase + nt * 8 + gid;
                b0[nt] = sW[kc0 * 256 + c * 4 + tig];
                b1[nt] = sW[kc1 * 256 + c * 4 + tig];
            }
#pragma unroll
            for (int mt = 0; mt < 2; mt++) {
                int r = mbase + mt * 16 + gid;
                uint32_t a0 = sA[kc0 * 516 + r * 4 + tig];
                uint32_t a1 = sA[kc0 * 516 + (r + 8) * 4 + tig];
                uint32_t a2 = sA[kc1 * 516 + r * 4 + tig];
                uint32_t a3 = sA[kc1 * 516 + (r + 8) * 4 + tig];
#pragma unroll
                for (int nt = 0; nt < 4; nt++)
                    mma_tf32(acc[mt][nt], a0, a1, a2, a3, b0[nt], b1[nt]);
            }
        }
    }

#pragma unroll
    for (int mt = 0; mt < 2; mt++) {
        int r0 = rowBase + mbase + mt * 16 + gid;
        int r1 = r0 + 8;
#pragma unroll
        for (int nt = 0; nt < 4; nt++) {
            int c = nbase + nt * 8 + 2 * tig;
            float bx = __ldg(bias + c), by = __ldg(bias + c + 1);
            if (r0 < N)
                *(__half2*)&g_hh[(size_t)r0 * H + c] =
                    __floats2half2_rn(acc[mt][nt][0] + bx,
                                      acc[mt][nt][1] + by);
            if (r1 < N)
                *(__half2*)&g_hh[(size_t)r1 * H + c] =
                    __floats2half2_rn(acc[mt][nt][2] + bx,
                                      acc[mt][nt][3] + by);
        }
    }
}

// ---------------------- persistent mega kernel: scan|scatter|agg|z|final
__global__ void __launch_bounds__(256, 6) mega_kernel(
    const int* __restrict__ row_idx, const int* __restrict__ col_idx,
    const float* __restrict__ vv, const float* __restrict__ wmlp,
    float* __restrict__ out, int N, int E, int nblocks) {
    __shared__ int sred[8];
    __shared__ int s_off;
    int tid = threadIdx.x;
    int lane = tid & 31, wid = tid >> 5;
    int bid = blockIdx.x;
    int nchunk = (N + 255) / 256;

    // ---- S1: per-chunk scan of g_cnt; self-reset g_cnt
    if (bid < nchunk) {
        int i = bid * 256 + tid;
        int c = (i < N) ? g_cnt[i] : 0;
        if (i < N) g_cnt[i] = 0;
        int x = c;
#pragma unroll
        for (int off = 1; off < 32; off <<= 1) {
            int t = __shfl_up_sync(0xFFFFFFFFu, x, off);
            if (lane >= off) x += t;
        }
        if (lane == 31) sred[wid] = x;
        __syncthreads();
        if (wid == 0) {
            int s = (lane < 8) ? sred[lane] : 0;
#pragma unroll
            for (int off = 1; off < 8; off <<= 1) {
                int t = __shfl_up_sync(0xFFFFFFFFu, s, off);
                if (lane >= off) s += t;
            }
            if (lane < 8) sred[lane] = s;
        }
        __syncthreads();
        int xincl = x + ((wid > 0) ? sred[wid - 1] : 0);
        if (i < N) g_part[i] = xincl - c;  // exclusive within chunk
        if (tid == 255) g_bagg[bid] = xincl;
    }
    grid_bar(nblocks);

    // ---- S2: chunk offsets -> g_start
    if (bid < nchunk) {
        int partial = 0;
        for (int j = tid; j < bid; j += 256) partial += g_bagg[j];
#pragma unroll
        for (int o = 16; o; o >>= 1)
            partial += __shfl_xor_sync(0xFFFFFFFFu, partial, o);
        if (lane == 0) sred[wid] = partial;
        __syncthreads();
        if (tid == 0) {
            int t = 0;
#pragma unroll
            for (int j = 0; j < 8; j++) t += sred[j];
            s_off = t;
        }
        __syncthreads();
        int i = bid * 256 + tid;
        if (i < N) g_start[i] = s_off + g_part[i];
        if (i == N - 1) g_start[N] = E;
    }
    grid_bar(nblocks);

    // ---- S3: atomic-free scatter into CSR (8B {col, v_bits})
    {
        int i = bid * 256 + tid;
        int stride = nblocks * 256;
        int E4 = E >> 2;
        const int4* r4 = (const int4*)row_idx;
        const int4* c4 = (const int4*)col_idx;
        const float4* v4 = (const float4*)vv;
        const int4* k4 = (const int4*)g_rank;
        for (int e = i; e < E4; e += stride) {
            int4 r = r4[e];
            int4 c = c4[e];
            float4 v = v4[e];
            int4 k = k4[e];
            g_ecsr[g_start[r.x] + k.x] = make_int2(c.x, __float_as_int(v.x));
            g_ecsr[g_start[r.y] + k.y] = make_int2(c.y, __float_as_int(v.y));
            g_ecsr[g_start[r.z] + k.z] = make_int2(c.z, __float_as_int(v.z));
            g_ecsr[g_start[r.w] + k.w] = make_int2(c.w, __float_as_int(v.w));
        }
        for (int e = E4 * 4 + i; e < E; e += stride)
            g_ecsr[g_start[row_idx[e]] + g_rank[e]] =
                make_int2(col_idx[e], __float_as_int(vv[e]));
    }
    grid_bar(nblocks);

    // ---- S4: agg + relu + dot(w2) + exp  (warp per row; half-warp per edge)
    {
        int half = lane >> 4;
        int seg = lane & 15;
        int gw = (bid * 256 + tid) >> 5;
        int nw = nblocks * 8;
        for (int w = gw; w < N; w += nw) {
            int s = g_start[w];
            int eend = g_start[w + 1];
            float4 acc = make_float4(0.f, 0.f, 0.f, 0.f);
            for (int p = s + half; p < eend; p += 2) {
                int2 ed = g_ecsr[p];  // broadcast within half-warp
                float v = __int_as_float(ed.y);
                uint2 u = *(const uint2*)(g_hh + (size_t)ed.x * H + seg * 4);
                float2 f01 = __half22float2(*(const __half2*)&u.x);
                float2 f23 = __half22float2(*(const __half2*)&u.y);
                acc.x = fmaf(v, f01.x, acc.x);
                acc.y = fmaf(v, f01.y, acc.y);
                acc.z = fmaf(v, f23.x, acc.z);
                acc.w = fmaf(v, f23.y, acc.w);
            }
            acc.x += __shfl_down_sync(0xFFFFFFFFu, acc.x, 16);
            acc.y += __shfl_down_sync(0xFFFFFFFFu, acc.y, 16);
            acc.z += __shfl_down_sync(0xFFFFFFFFu, acc.z, 16);
            acc.w += __shfl_down_sync(0xFFFFFFFFu, acc.w, 16);
            float pd = 0.0f;
            if (half == 0) {
                float4 w2 = *(const float4*)(wmlp + H + seg * 4);
                pd = fmaxf(acc.x, 0.f) * w2.x + fmaxf(acc.y, 0.f) * w2.y +
                     fmaxf(acc.z, 0.f) * w2.z + fmaxf(acc.w, 0.f) * w2.w;
            }
#pragma unroll
            for (int o = 8; o; o >>= 1)
                pd += __shfl_down_sync(0xFFFFFFFFu, pd, o);
            if (lane == 0) g_ex[w] = __expf(pd);
        }
    }
    grid_bar(nblocks);

    // ---- S5: per-row Z (HALF-warp per row; 16-lane gather); store 1/Z
    {
        int seg = lane & 15;
        int ghw = (bid * 256 + tid) >> 4;  // global half-warp id
        int nhw = nblocks * 16;
        for (int w = ghw; w < N; w += nhw) {
            int s = g_start[w];
            int eend = g_start[w + 1];
            if (s == eend) continue;
            float z = 0.0f;
            for (int p = s + seg; p < eend; p += 16) z += g_ex[g_ecsr[p].x];
#pragma unroll
            for (int o = 8; o; o >>= 1)
                z += __shfl_xor_sync(0xFFFFFFFFu, z, o);
            if (seg == 0) g_rz[w] = 1.0f / z;
        }
    }
    grid_bar(nblocks);

    // ---- S6: final, original edge order (coalesced): out = v + ex*rz
    {
        int i = bid * 256 + tid;
        int stride = nblocks * 256;
        int E4 = E >> 2;
        const int4* r4 = (const int4*)row_idx;
        const int4* c4 = (const int4*)col_idx;
        const float4* v4 = (const float4*)vv;
        float4* o4 = (float4*)out;
        for (int e = i; e < E4; e += stride) {
            int4 r = r4[e];
            int4 c = c4[e];
            float4 v = v4[e];
            float4 o;
            o.x = fmaf(g_ex[c.x], g_rz[r.x], v.x);
            o.y = fmaf(g_ex[c.y], g_rz[r.y], v.y);
            o.z = fmaf(g_ex[c.z], g_rz[r.z], v.z);
            o.w = fmaf(g_ex[c.w], g_rz[r.w], v.w);
            o4[e] = o;
        }
        for (int e = E4 * 4 + i; e < E; e += stride)
            out[e] = fmaf(g_ex[col_idx[e]], g_rz[row_idx[e]], vv[e]);
    }
}

// ---------------------------------------------------------------- launch
extern "C" void kernel_launch(void* const* d_in, const int* in_sizes, int n_in,
                              void* d_out, int out_size) {
    const float* feat = (const float*)d_in[0];
    const float* vv = (const float*)d_in[1];
    const float* W = (const float*)d_in[2];
    const float* bg = (const float*)d_in[3];
    const float* wm = (const float*)d_in[4];
    // d_in[5] = b_mlp: cancels in softmax; unused.
    const int* vidx = (const int*)d_in[6];  // int32 (JAX x64 disabled)

    int F = in_sizes[2] / H;  // 256
    int N = in_sizes[0] / F;  // 100000
    int E = in_sizes[1];      // 1600000
    const int* row_idx = vidx;
    const int* col_idx = vidx + E;
    float* out = (float*)d_out;

    int G = (N + 127) / 128;  // gemm blocks
    int HB = 1024;            // hist blocks

    int smcount = 0, bpsm = 0;
    cudaDeviceGetAttribute(&smcount, cudaDevAttrMultiProcessorCount, 0);
    cudaOccupancyMaxActiveBlocksPerMultiprocessor(&bpsm, mega_kernel, 256, 0);
    if (bpsm > 6) bpsm = 6;
    if (bpsm < 1) bpsm = 1;
    int nblocks = smcount * bpsm;
    int nchunk = (N + 255) / 256;
    if (nblocks < nchunk) nblocks = nchunk;

    size_t smem = (size_t)(8 * 516 + 2048) * 4;  // A staging + W tile (24.7KB)

    gemm_hist_kernel<<<G + HB, 256, smem>>>(feat, W, bg, row_idx, N, F, E, G);
    mega_kernel<<<nblocks, 256>>>(row_idx, col_idx, vv, wm, out, N, E,
                                  nblocks);
}